// round 2
// baseline (speedup 1.0000x reference)
#include <cuda_runtime.h>
#include <cstdint>

#define CC 64
#define NSN 16
#define MAXN 65536

// Scratch for q/k/v projections (48 MB total) — __device__ globals per harness rules.
__device__ float g_xq[MAXN * CC];
__device__ float g_xk[MAXN * CC];
__device__ float g_xv[MAXN * CC];

// ---------------------------------------------------------------------------
// Kernel A: xq = x@Wq+bq, xk = x@Wk+bk, xv = x@Wv+bv   (three 64x64 GEMMs)
// Block: 128 threads, 64 rows. Per-matrix W staged in SMEM (16KB), X staged
// once (16.6KB). Thread tile: 4 rows x 8 cols.
// ---------------------------------------------------------------------------
__global__ __launch_bounds__(128) void qkv_kernel(
    const float* __restrict__ x,
    const float* __restrict__ Wq, const float* __restrict__ bq,
    const float* __restrict__ Wk, const float* __restrict__ bk,
    const float* __restrict__ Wv, const float* __restrict__ bv)
{
    __shared__ float Xs[64 * 65];
    __shared__ float Ws[64 * 64];
    __shared__ float Bs[64];

    const int tid = threadIdx.x;
    const int r0  = blockIdx.x * 64;

    // Stage X tile (64 rows x 64 cols), padded stride 65 to dodge bank conflicts.
    for (int idx = tid; idx < 64 * 16; idx += 128) {
        int r = idx >> 4, k4 = (idx & 15) * 4;
        float4 v = *(const float4*)(x + (size_t)(r0 + r) * 64 + k4);
        Xs[r * 65 + k4 + 0] = v.x;
        Xs[r * 65 + k4 + 1] = v.y;
        Xs[r * 65 + k4 + 2] = v.z;
        Xs[r * 65 + k4 + 3] = v.w;
    }

    const float* Wm[3] = {Wq, Wk, Wv};
    const float* bm[3] = {bq, bk, bv};
    float*       dm[3] = {g_xq, g_xk, g_xv};

    const int tx = tid & 7;   // col group: cols tx*8 .. tx*8+7
    const int ty = tid >> 3;  // rows ty + 16*j, j=0..3

    for (int m = 0; m < 3; m++) {
        __syncthreads();  // Xs ready / previous Ws consumers done
        for (int idx = tid; idx < 64 * 16; idx += 128)
            ((float4*)Ws)[idx] = ((const float4*)Wm[m])[idx];
        if (tid < 64) Bs[tid] = bm[m][tid];
        __syncthreads();

        float acc[4][8];
        #pragma unroll
        for (int j = 0; j < 4; j++)
            #pragma unroll
            for (int i = 0; i < 8; i++) acc[j][i] = 0.f;

        #pragma unroll 4
        for (int k = 0; k < 64; k++) {
            float xa[4];
            #pragma unroll
            for (int j = 0; j < 4; j++) xa[j] = Xs[(ty + 16 * j) * 65 + k];
            float4 w0 = *(const float4*)(Ws + k * 64 + tx * 8);
            float4 w1 = *(const float4*)(Ws + k * 64 + tx * 8 + 4);
            float wb[8] = {w0.x, w0.y, w0.z, w0.w, w1.x, w1.y, w1.z, w1.w};
            #pragma unroll
            for (int j = 0; j < 4; j++)
                #pragma unroll
                for (int i = 0; i < 8; i++)
                    acc[j][i] = fmaf(xa[j], wb[i], acc[j][i]);
        }

        float* dst = dm[m];
        float b[8];
        #pragma unroll
        for (int i = 0; i < 8; i++) b[i] = Bs[tx * 8 + i];
        #pragma unroll
        for (int j = 0; j < 4; j++) {
            size_t off = (size_t)(r0 + ty + 16 * j) * 64 + tx * 8;
            float4 o0 = make_float4(acc[j][0] + b[0], acc[j][1] + b[1],
                                    acc[j][2] + b[2], acc[j][3] + b[3]);
            float4 o1 = make_float4(acc[j][4] + b[4], acc[j][5] + b[5],
                                    acc[j][6] + b[6], acc[j][7] + b[7]);
            *(float4*)(dst + off)     = o0;
            *(float4*)(dst + off + 4) = o1;
        }
    }
}

// ---------------------------------------------------------------------------
// Kernel B: full attention per point.
// Block = 256 threads = 16 points x 16 neighbors.
// Phase 1 (thread = (point, neighbor)): position MLP, fused BN1+logits MLP,
//   softmax over 16 neighbors via shfl within aligned 16-lane groups.
// Phase 2 (thread = (point, 4 channels)): weighted gather-sum of (xv + pr).
// ---------------------------------------------------------------------------
__global__ __launch_bounds__(256) void attn_kernel(
    const float* __restrict__ p,
    const int*   __restrict__ nidx,
    const float* __restrict__ p1_W, const float* __restrict__ p1_b,
    const float* __restrict__ p_g,  const float* __restrict__ p_b,
    const float* __restrict__ p2_W, const float* __restrict__ p2_b,
    const float* __restrict__ w_g1, const float* __restrict__ w_b1,
    const float* __restrict__ w1_W, const float* __restrict__ w1_b,
    const float* __restrict__ w_g2, const float* __restrict__ w_b2,
    const float* __restrict__ w2_W, const float* __restrict__ w2_b,
    float* __restrict__ out)
{
    __shared__ float4 s_p2s[64];       // (p2W0*s1, p2W1*s1, p2W2*s1, s1) per channel
    __shared__ float4 s_p2r[64];       // (p2W0, p2W1, p2W2, p2_b) per channel (raw, for phase 2)
    __shared__ float4 s_w1[128];       // w1_W[c][0..7] as two float4 per channel
    __shared__ float4 s_base[16][17];  // per point: b1 + (p2_b - xq)*s1, 4 channels per float4
    __shared__ float4 s_h[16][16];     // h0,h1,h2 per (point, neighbor)
    __shared__ float  s_wt[16][136];   // attention weights, [pt][cs*17 + ns]
    __shared__ int    s_idx[16][17];
    __shared__ float  s_p1W[9], s_p1b[3], s_sp[3], s_pb[3];
    __shared__ float  s_s2[8], s_b2[8], s_w1b[8], s_w2b[8];
    __shared__ float  s_w2[64];

    const int tid  = threadIdx.x;
    const int blk0 = blockIdx.x * 16;
    const float inv = rsqrtf(1.0f + 1e-5f);

    // ---- stage weights (fold BN scales) ----
    if (tid < 9) s_p1W[tid] = p1_W[tid];
    if (tid < 3) { s_p1b[tid] = p1_b[tid]; s_sp[tid] = p_g[tid] * inv; s_pb[tid] = p_b[tid]; }
    if (tid < 8) {
        s_s2[tid]  = w_g2[tid] * inv;
        s_b2[tid]  = w_b2[tid];
        s_w1b[tid] = w1_b[tid];
        s_w2b[tid] = w2_b[tid];
    }
    if (tid < 64) {
        s_w2[tid] = w2_W[tid];
        float s1v = w_g1[tid] * inv;
        float a0 = p2_W[tid], a1 = p2_W[64 + tid], a2 = p2_W[128 + tid];
        s_p2r[tid] = make_float4(a0, a1, a2, p2_b[tid]);
        s_p2s[tid] = make_float4(a0 * s1v, a1 * s1v, a2 * s1v, s1v);
        s_w1[tid * 2]     = make_float4(w1_W[tid * 8 + 0], w1_W[tid * 8 + 1],
                                        w1_W[tid * 8 + 2], w1_W[tid * 8 + 3]);
        s_w1[tid * 2 + 1] = make_float4(w1_W[tid * 8 + 4], w1_W[tid * 8 + 5],
                                        w1_W[tid * 8 + 6], w1_W[tid * 8 + 7]);
    }
    // per-(point, channel) base term: b1 + (p2_b - xq)*s1
    for (int idx = tid; idx < 16 * 64; idx += 256) {
        int ptl = idx >> 6, c = idx & 63;
        float s1v  = w_g1[c] * inv;
        float base = w_b1[c] + (p2_b[c] - g_xq[(size_t)(blk0 + ptl) * 64 + c]) * s1v;
        ((float*)&s_base[ptl][0])[c] = base;
    }
    __syncthreads();

    // ---- phase 1: thread = (point, neighbor) ----
    const int ptl = tid >> 4, ln = tid & 15;
    const int pt  = blk0 + ptl;
    const int j   = nidx[pt * NSN + ln];
    s_idx[ptl][ln] = j;

    float dp0 = p[j * 3 + 0] - p[pt * 3 + 0];
    float dp1 = p[j * 3 + 1] - p[pt * 3 + 1];
    float dp2 = p[j * 3 + 2] - p[pt * 3 + 2];

    float h0, h1, h2;
    {
        float v0 = dp0 * s_p1W[0] + dp1 * s_p1W[3] + dp2 * s_p1W[6] + s_p1b[0];
        float v1 = dp0 * s_p1W[1] + dp1 * s_p1W[4] + dp2 * s_p1W[7] + s_p1b[1];
        float v2 = dp0 * s_p1W[2] + dp1 * s_p1W[5] + dp2 * s_p1W[8] + s_p1b[2];
        h0 = fmaxf(v0 * s_sp[0] + s_pb[0], 0.f);
        h1 = fmaxf(v1 * s_sp[1] + s_pb[1], 0.f);
        h2 = fmaxf(v2 * s_sp[2] + s_pb[2], 0.f);
    }
    s_h[ptl][ln] = make_float4(h0, h1, h2, 0.f);

    float acc[8];
    #pragma unroll
    for (int q = 0; q < 8; q++) acc[q] = 0.f;

    const float4* xk4   = (const float4*)(g_xk + (size_t)j * 64);
    const float4* base4 = &s_base[ptl][0];
    #pragma unroll
    for (int c4 = 0; c4 < 16; c4++) {
        float4 gk = xk4[c4];
        float4 bb = base4[c4];
        float gv[4] = {gk.x, gk.y, gk.z, gk.w};
        float bl[4] = {bb.x, bb.y, bb.z, bb.w};
        #pragma unroll
        for (int q = 0; q < 4; q++) {
            int c = c4 * 4 + q;
            float4 ps = s_p2s[c];
            // a = relu( (gk - xq + pr)*s1 + b1 ), all folded:
            float a = fmaxf(fmaf(gv[q], ps.w,
                          fmaf(h0, ps.x, fmaf(h1, ps.y, fmaf(h2, ps.z, bl[q])))), 0.f);
            float4 wA = s_w1[c * 2];
            float4 wB = s_w1[c * 2 + 1];
            acc[0] = fmaf(a, wA.x, acc[0]);
            acc[1] = fmaf(a, wA.y, acc[1]);
            acc[2] = fmaf(a, wA.z, acc[2]);
            acc[3] = fmaf(a, wA.w, acc[3]);
            acc[4] = fmaf(a, wB.x, acc[4]);
            acc[5] = fmaf(a, wB.y, acc[5]);
            acc[6] = fmaf(a, wB.z, acc[6]);
            acc[7] = fmaf(a, wB.w, acc[7]);
        }
    }

    // BN2 + ReLU + w2
    float lg[8];
    {
        float u[8];
        #pragma unroll
        for (int q = 0; q < 8; q++)
            u[q] = fmaxf(fmaf(acc[q] + s_w1b[q], s_s2[q], s_b2[q]), 0.f);
        #pragma unroll
        for (int r = 0; r < 8; r++) {
            float s = s_w2b[r];
            #pragma unroll
            for (int q = 0; q < 8; q++) s = fmaf(u[q], s_w2[q * 8 + r], s);
            lg[r] = s;
        }
    }

    // softmax over the 16 neighbors (aligned 16-lane group within the warp)
    #pragma unroll
    for (int r = 0; r < 8; r++) {
        float m = lg[r];
        m = fmaxf(m, __shfl_xor_sync(0xffffffffu, m, 1));
        m = fmaxf(m, __shfl_xor_sync(0xffffffffu, m, 2));
        m = fmaxf(m, __shfl_xor_sync(0xffffffffu, m, 4));
        m = fmaxf(m, __shfl_xor_sync(0xffffffffu, m, 8));
        float e = __expf(lg[r] - m);
        float s = e;
        s += __shfl_xor_sync(0xffffffffu, s, 1);
        s += __shfl_xor_sync(0xffffffffu, s, 2);
        s += __shfl_xor_sync(0xffffffffu, s, 4);
        s += __shfl_xor_sync(0xffffffffu, s, 8);
        s_wt[ptl][r * 17 + ln] = e / s;
    }
    __syncthreads();

    // ---- phase 2: thread = (point, 4 channels), coalesced xv gather ----
    int idxr[16];
    #pragma unroll
    for (int ns = 0; ns < 16; ns++) idxr[ns] = s_idx[ptl][ns];

    const int cs = ln & 7;
    #pragma unroll
    for (int i = 0; i < 4; i++) {
        int c = ln + 16 * i;
        float4 pr4 = s_p2r[c];
        float sum = 0.f;
        #pragma unroll
        for (int ns = 0; ns < 16; ns++) {
            float4 hh  = s_h[ptl][ns];
            float prc  = fmaf(hh.x, pr4.x, fmaf(hh.y, pr4.y, fmaf(hh.z, pr4.z, pr4.w)));
            float gvv  = g_xv[(size_t)idxr[ns] * 64 + c];
            sum = fmaf(gvv + prc, s_wt[ptl][cs * 17 + ns], sum);
        }
        out[(size_t)pt * 64 + c] = sum;
    }
}

// ---------------------------------------------------------------------------
extern "C" void kernel_launch(void* const* d_in, const int* in_sizes, int n_in,
                              void* d_out, int out_size)
{
    const float* p    = (const float*)d_in[0];
    const float* x    = (const float*)d_in[1];
    const int*   nidx = (const int*)  d_in[2];
    const float* Wq   = (const float*)d_in[3];
    const float* bq   = (const float*)d_in[4];
    const float* Wk   = (const float*)d_in[5];
    const float* bk   = (const float*)d_in[6];
    const float* Wv   = (const float*)d_in[7];
    const float* bv   = (const float*)d_in[8];
    const float* p1W  = (const float*)d_in[9];
    const float* p1b  = (const float*)d_in[10];
    const float* pg   = (const float*)d_in[11];
    const float* pb   = (const float*)d_in[12];
    const float* p2W  = (const float*)d_in[13];
    const float* p2b  = (const float*)d_in[14];
    const float* wg1  = (const float*)d_in[15];
    const float* wb1  = (const float*)d_in[16];
    const float* w1W  = (const float*)d_in[17];
    const float* w1b  = (const float*)d_in[18];
    const float* wg2  = (const float*)d_in[19];
    const float* wb2  = (const float*)d_in[20];
    const float* w2W  = (const float*)d_in[21];
    const float* w2b  = (const float*)d_in[22];
    float* out = (float*)d_out;

    const int N = in_sizes[1] / CC;   // 65536

    qkv_kernel<<<N / 64, 128>>>(x, Wq, bq, Wk, bk, Wv, bv);
    attn_kernel<<<N / 16, 256>>>(p, nidx,
                                 p1W, p1b, pg, pb, p2W, p2b,
                                 wg1, wb1, w1W, w1b, wg2, wb2, w2W, w2b,
                                 out);
}

// round 3
// speedup vs baseline: 1.1945x; 1.1945x over previous
#include <cuda_runtime.h>
#include <cstdint>

#define CC 64
#define NSN 16
#define MAXN 65536

// Scratch for q/k/v projections — __device__ globals per harness rules.
__device__ float g_xq[MAXN * CC];
__device__ float g_xk[MAXN * CC];
__device__ float g_xv[MAXN * CC];

// ---------------------------------------------------------------------------
// Kernel A: xq = x@Wq+bq, xk = x@Wk+bk, xv = x@Wv+bv   (three 64x64 GEMMs)
// ---------------------------------------------------------------------------
__global__ __launch_bounds__(128) void qkv_kernel(
    const float* __restrict__ x,
    const float* __restrict__ Wq, const float* __restrict__ bq,
    const float* __restrict__ Wk, const float* __restrict__ bk,
    const float* __restrict__ Wv, const float* __restrict__ bv)
{
    __shared__ float Xs[64 * 65];
    __shared__ float Ws[64 * 64];
    __shared__ float Bs[64];

    const int tid = threadIdx.x;
    const int r0  = blockIdx.x * 64;

    for (int idx = tid; idx < 64 * 16; idx += 128) {
        int r = idx >> 4, k4 = (idx & 15) * 4;
        float4 v = *(const float4*)(x + (size_t)(r0 + r) * 64 + k4);
        Xs[r * 65 + k4 + 0] = v.x;
        Xs[r * 65 + k4 + 1] = v.y;
        Xs[r * 65 + k4 + 2] = v.z;
        Xs[r * 65 + k4 + 3] = v.w;
    }

    const float* Wm[3] = {Wq, Wk, Wv};
    const float* bm[3] = {bq, bk, bv};
    float*       dm[3] = {g_xq, g_xk, g_xv};

    const int tx = tid & 7;
    const int ty = tid >> 3;

    for (int m = 0; m < 3; m++) {
        __syncthreads();
        for (int idx = tid; idx < 64 * 16; idx += 128)
            ((float4*)Ws)[idx] = ((const float4*)Wm[m])[idx];
        if (tid < 64) Bs[tid] = bm[m][tid];
        __syncthreads();

        float acc[4][8];
        #pragma unroll
        for (int j = 0; j < 4; j++)
            #pragma unroll
            for (int i = 0; i < 8; i++) acc[j][i] = 0.f;

        #pragma unroll 4
        for (int k = 0; k < 64; k++) {
            float xa[4];
            #pragma unroll
            for (int j = 0; j < 4; j++) xa[j] = Xs[(ty + 16 * j) * 65 + k];
            float4 w0 = *(const float4*)(Ws + k * 64 + tx * 8);
            float4 w1 = *(const float4*)(Ws + k * 64 + tx * 8 + 4);
            float wb[8] = {w0.x, w0.y, w0.z, w0.w, w1.x, w1.y, w1.z, w1.w};
            #pragma unroll
            for (int j = 0; j < 4; j++)
                #pragma unroll
                for (int i = 0; i < 8; i++)
                    acc[j][i] = fmaf(xa[j], wb[i], acc[j][i]);
        }

        float* dst = dm[m];
        float b[8];
        #pragma unroll
        for (int i = 0; i < 8; i++) b[i] = Bs[tx * 8 + i];
        #pragma unroll
        for (int j = 0; j < 4; j++) {
            size_t off = (size_t)(r0 + ty + 16 * j) * 64 + tx * 8;
            float4 o0 = make_float4(acc[j][0] + b[0], acc[j][1] + b[1],
                                    acc[j][2] + b[2], acc[j][3] + b[3]);
            float4 o1 = make_float4(acc[j][4] + b[4], acc[j][5] + b[5],
                                    acc[j][6] + b[6], acc[j][7] + b[7]);
            *(float4*)(dst + off)     = o0;
            *(float4*)(dst + off + 4) = o1;
        }
    }
}

// ---------------------------------------------------------------------------
// Kernel B: attention. 16 points x 16 neighbors per block (256 threads).
// k rows staged cooperatively into SMEM (2 chunks of 32 channels) so the
// irregular gather is coalesced (128B per 8-lane group). Row stride 33 words
// makes per-thread compute reads bank-conflict-free.
// The k-tile SMEM region is reused for the attention weights after phase 1.
// ---------------------------------------------------------------------------
__global__ __launch_bounds__(256, 3) void attn_kernel(
    const float* __restrict__ p,
    const int*   __restrict__ nidx,
    const float* __restrict__ p1_W, const float* __restrict__ p1_b,
    const float* __restrict__ p_g,  const float* __restrict__ p_b,
    const float* __restrict__ p2_W, const float* __restrict__ p2_b,
    const float* __restrict__ w_g1, const float* __restrict__ w_b1,
    const float* __restrict__ w1_W, const float* __restrict__ w1_b,
    const float* __restrict__ w_g2, const float* __restrict__ w_b2,
    const float* __restrict__ w2_W, const float* __restrict__ w2_b,
    float* __restrict__ out)
{
    __shared__ float  s_un[256 * 33];   // k tile (chunked) -> later attn weights
    __shared__ int    s_idx[256];
    __shared__ float  s_h0[256], s_h1[256], s_h2[256];
    __shared__ float4 s_base4[256];     // [pt][16] : b1 + (p2_b - xq)*s1
    __shared__ float4 s_p2s[64];        // (p2W*s1, s1) per channel
    __shared__ float4 s_p2r[64];        // raw (p2W0,p2W1,p2W2,p2_b)
    __shared__ float4 s_w1[128];        // w1_W rows as 2x float4
    __shared__ float  s_w2[64];
    __shared__ float  s_s2[8], s_b2[8], s_w1b[8], s_w2b[8];
    __shared__ float  s_p1W[9], s_p1b[3], s_sp[3], s_pb[3];

    const int tid  = threadIdx.x;
    const int blk0 = blockIdx.x * 16;
    const float inv = rsqrtf(1.0f + 1e-5f);

    // ---- stage weights (fold BN scales) ----
    if (tid < 9) s_p1W[tid] = p1_W[tid];
    if (tid < 3) { s_p1b[tid] = p1_b[tid]; s_sp[tid] = p_g[tid] * inv; s_pb[tid] = p_b[tid]; }
    if (tid < 8) {
        s_s2[tid]  = w_g2[tid] * inv;
        s_b2[tid]  = w_b2[tid];
        s_w1b[tid] = w1_b[tid];
        s_w2b[tid] = w2_b[tid];
    }
    if (tid < 64) {
        s_w2[tid] = w2_W[tid];
        float s1v = w_g1[tid] * inv;
        float a0 = p2_W[tid], a1 = p2_W[64 + tid], a2 = p2_W[128 + tid];
        s_p2r[tid] = make_float4(a0, a1, a2, p2_b[tid]);
        s_p2s[tid] = make_float4(a0 * s1v, a1 * s1v, a2 * s1v, s1v);
        s_w1[tid * 2]     = make_float4(w1_W[tid * 8 + 0], w1_W[tid * 8 + 1],
                                        w1_W[tid * 8 + 2], w1_W[tid * 8 + 3]);
        s_w1[tid * 2 + 1] = make_float4(w1_W[tid * 8 + 4], w1_W[tid * 8 + 5],
                                        w1_W[tid * 8 + 6], w1_W[tid * 8 + 7]);
    }
    // per-(point, channel) base term: b1 + (p2_b - xq)*s1
    for (int idx = tid; idx < 16 * 64; idx += 256) {
        int ptl = idx >> 6, c = idx & 63;
        float s1v  = w_g1[c] * inv;
        float base = w_b1[c] + (p2_b[c] - g_xq[(size_t)(blk0 + ptl) * 64 + c]) * s1v;
        ((float*)s_base4)[ptl * 64 + c] = base;
    }

    const int ptl = tid >> 4, ln = tid & 15;
    const int pt  = blk0 + ptl;
    const int j   = nidx[pt * NSN + ln];
    s_idx[tid] = j;

    // position MLP: h = relu(BN((pj - pi) @ p1_W + p1_b))
    float h0, h1, h2;
    {
        float dp0 = p[j * 3 + 0] - p[pt * 3 + 0];
        float dp1 = p[j * 3 + 1] - p[pt * 3 + 1];
        float dp2 = p[j * 3 + 2] - p[pt * 3 + 2];
        float v0 = dp0 * s_p1W[0] + dp1 * s_p1W[3] + dp2 * s_p1W[6] + s_p1b[0];
        float v1 = dp0 * s_p1W[1] + dp1 * s_p1W[4] + dp2 * s_p1W[7] + s_p1b[1];
        float v2 = dp0 * s_p1W[2] + dp1 * s_p1W[5] + dp2 * s_p1W[8] + s_p1b[2];
        h0 = fmaxf(v0 * s_sp[0] + s_pb[0], 0.f);
        h1 = fmaxf(v1 * s_sp[1] + s_pb[1], 0.f);
        h2 = fmaxf(v2 * s_sp[2] + s_pb[2], 0.f);
    }
    s_h0[tid] = h0; s_h1[tid] = h1; s_h2[tid] = h2;
    __syncthreads();

    // ---- phase 1: fused BN1 + logits MLP over 2 staged 32-channel chunks ----
    float acc[8];
    #pragma unroll
    for (int q = 0; q < 8; q++) acc[q] = 0.f;

    #pragma unroll
    for (int ch = 0; ch < 2; ch++) {
        if (ch) __syncthreads();  // chunk-0 reads done before overwrite
        // cooperative coalesced stage: 8-lane groups load 128B row chunks
        {
            const int q8  = tid & 7;
            const int rb  = tid >> 3;
            #pragma unroll
            for (int i = 0; i < 8; i++) {
                int row = rb + 32 * i;
                int jj  = s_idx[row];
                float4 v = *(const float4*)(g_xk + (size_t)jj * 64 + ch * 32 + q8 * 4);
                float* d = s_un + row * 33 + q8 * 4;
                d[0] = v.x; d[1] = v.y; d[2] = v.z; d[3] = v.w;
            }
        }
        __syncthreads();

        const float* krow = s_un + tid * 33;
        #pragma unroll
        for (int c4 = 0; c4 < 8; c4++) {
            int cq = ch * 8 + c4;
            float4 bb = s_base4[ptl * 16 + cq];
            float bl[4] = {bb.x, bb.y, bb.z, bb.w};
            #pragma unroll
            for (int q = 0; q < 4; q++) {
                int c = cq * 4 + q;
                float gk = krow[c4 * 4 + q];
                float4 ps = s_p2s[c];
                float a = fmaxf(fmaf(gk, ps.w,
                              fmaf(h0, ps.x, fmaf(h1, ps.y, fmaf(h2, ps.z, bl[q])))), 0.f);
                float4 wA = s_w1[c * 2];
                float4 wB = s_w1[c * 2 + 1];
                acc[0] = fmaf(a, wA.x, acc[0]);
                acc[1] = fmaf(a, wA.y, acc[1]);
                acc[2] = fmaf(a, wA.z, acc[2]);
                acc[3] = fmaf(a, wA.w, acc[3]);
                acc[4] = fmaf(a, wB.x, acc[4]);
                acc[5] = fmaf(a, wB.y, acc[5]);
                acc[6] = fmaf(a, wB.z, acc[6]);
                acc[7] = fmaf(a, wB.w, acc[7]);
            }
        }
    }
    __syncthreads();  // all k reads done before s_un is reused for weights

    // BN2 + ReLU + w2 -> 8 logits
    float lg[8];
    {
        float u[8];
        #pragma unroll
        for (int q = 0; q < 8; q++)
            u[q] = fmaxf(fmaf(acc[q] + s_w1b[q], s_s2[q], s_b2[q]), 0.f);
        #pragma unroll
        for (int r = 0; r < 8; r++) {
            float s = s_w2b[r];
            #pragma unroll
            for (int q = 0; q < 8; q++) s = fmaf(u[q], s_w2[q * 8 + r], s);
            lg[r] = s;
        }
    }

    // softmax over the 16 neighbors (aligned 16-lane group)
    float* s_wt = s_un;  // [pt*136 + r*17 + ns]
    #pragma unroll
    for (int r = 0; r < 8; r++) {
        float m = lg[r];
        m = fmaxf(m, __shfl_xor_sync(0xffffffffu, m, 1));
        m = fmaxf(m, __shfl_xor_sync(0xffffffffu, m, 2));
        m = fmaxf(m, __shfl_xor_sync(0xffffffffu, m, 4));
        m = fmaxf(m, __shfl_xor_sync(0xffffffffu, m, 8));
        float e = __expf(lg[r] - m);
        float s = e;
        s += __shfl_xor_sync(0xffffffffu, s, 1);
        s += __shfl_xor_sync(0xffffffffu, s, 2);
        s += __shfl_xor_sync(0xffffffffu, s, 4);
        s += __shfl_xor_sync(0xffffffffu, s, 8);
        s_wt[ptl * 136 + r * 17 + ln] = __fdividef(e, s);
    }
    __syncthreads();

    // ---- phase 2: thread = (point, 4 channels), neighbor-outer loop ----
    float4 pr4[4];
    #pragma unroll
    for (int i = 0; i < 4; i++) pr4[i] = s_p2r[ln + 16 * i];

    float sum[4] = {0.f, 0.f, 0.f, 0.f};
    const int cs = ln & 7;
    #pragma unroll
    for (int ns = 0; ns < 16; ns++) {
        int   jj = s_idx[ptl * 16 + ns];
        float hh0 = s_h0[ptl * 16 + ns];
        float hh1 = s_h1[ptl * 16 + ns];
        float hh2 = s_h2[ptl * 16 + ns];
        float wt  = s_wt[ptl * 136 + cs * 17 + ns];
        const float* vrow = g_xv + (size_t)jj * 64;
        #pragma unroll
        for (int i = 0; i < 4; i++) {
            int c = ln + 16 * i;
            float prc = fmaf(hh0, pr4[i].x,
                        fmaf(hh1, pr4[i].y,
                        fmaf(hh2, pr4[i].z, pr4[i].w)));
            sum[i] = fmaf(vrow[c] + prc, wt, sum[i]);
        }
    }
    #pragma unroll
    for (int i = 0; i < 4; i++)
        out[(size_t)pt * 64 + ln + 16 * i] = sum[i];
}

// ---------------------------------------------------------------------------
extern "C" void kernel_launch(void* const* d_in, const int* in_sizes, int n_in,
                              void* d_out, int out_size)
{
    const float* p    = (const float*)d_in[0];
    const float* x    = (const float*)d_in[1];
    const int*   nidx = (const int*)  d_in[2];
    const float* Wq   = (const float*)d_in[3];
    const float* bq   = (const float*)d_in[4];
    const float* Wk   = (const float*)d_in[5];
    const float* bk   = (const float*)d_in[6];
    const float* Wv   = (const float*)d_in[7];
    const float* bv   = (const float*)d_in[8];
    const float* p1W  = (const float*)d_in[9];
    const float* p1b  = (const float*)d_in[10];
    const float* pg   = (const float*)d_in[11];
    const float* pb   = (const float*)d_in[12];
    const float* p2W  = (const float*)d_in[13];
    const float* p2b  = (const float*)d_in[14];
    const float* wg1  = (const float*)d_in[15];
    const float* wb1  = (const float*)d_in[16];
    const float* w1W  = (const float*)d_in[17];
    const float* w1b  = (const float*)d_in[18];
    const float* wg2  = (const float*)d_in[19];
    const float* wb2  = (const float*)d_in[20];
    const float* w2W  = (const float*)d_in[21];
    const float* w2b  = (const float*)d_in[22];
    float* out = (float*)d_out;

    const int N = in_sizes[1] / CC;   // 65536

    qkv_kernel<<<N / 64, 128>>>(x, Wq, bq, Wk, bk, Wv, bv);
    attn_kernel<<<N / 16, 256>>>(p, nidx,
                                 p1W, p1b, pg, pb, p2W, p2b,
                                 wg1, wb1, w1W, w1b, wg2, wb2, w2W, w2b,
                                 out);
}

// round 5
// speedup vs baseline: 1.4215x; 1.1900x over previous
#include <cuda_runtime.h>
#include <cstdint>

#define CC 64
#define NSN 16
#define MAXN 65536

typedef unsigned long long u64;

// Scratch for q/k/v projections — __device__ globals per harness rules.
__device__ float g_xq[MAXN * CC];
__device__ float g_xk[MAXN * CC];
__device__ float g_xv[MAXN * CC];

// Folded-weight struct: lives in a __device__ global (for divergent access)
// and is copied to __constant__ (for uniform access via the const port).
struct FW {
    float4 p2s[64];     // (p2W0*s1, p2W1*s1, p2W2*s1, s1) per channel
    float4 p2r[64];     // (p2W0, p2W1, p2W2, p2_b) raw
    float2 w1p[256];    // w1[c][2q], w1[c][2q+1]  (c*4+q)
    float  w2[64];      // w2_W[q*8+r]
    float  s2[8], c2[8], w2b[8];
    float  pA[9], pc[3];   // folded position MLP layer 1
    float  b1f[64], s1v[64];
};
__device__ FW g_fold;
__constant__ FW c_cw;

// ---- f32x2 helpers (Blackwell packed fp32) ----
__device__ __forceinline__ void ffma2(u64& d, u64 a, u64 b) {
    asm("fma.rn.f32x2 %0, %1, %2, %0;" : "+l"(d) : "l"(a), "l"(b));
}
__device__ __forceinline__ u64 pk2(float x, float y) {
    u64 r; asm("mov.b64 %0, {%1, %2};" : "=l"(r) : "f"(x), "f"(y)); return r;
}
__device__ __forceinline__ float2 upk2(u64 v) {
    float2 r; asm("mov.b64 {%0, %1}, %2;" : "=f"(r.x), "=f"(r.y) : "l"(v)); return r;
}

// ---------------------------------------------------------------------------
// Fold kernel: pre-fold BN scales into g_fold (then D2D copy to c_cw).
// ---------------------------------------------------------------------------
__global__ void fold_kernel(
    const float* __restrict__ p1_W, const float* __restrict__ p1_b,
    const float* __restrict__ p_g,  const float* __restrict__ p_b,
    const float* __restrict__ p2_W, const float* __restrict__ p2_b,
    const float* __restrict__ w_g1, const float* __restrict__ w_b1,
    const float* __restrict__ w1_W, const float* __restrict__ w1_b,
    const float* __restrict__ w_g2, const float* __restrict__ w_b2,
    const float* __restrict__ w2_W, const float* __restrict__ w2_b)
{
    const int t = threadIdx.x;
    const float inv = rsqrtf(1.0f + 1e-5f);
    if (t < 64) {
        float s1 = w_g1[t] * inv;
        float a0 = p2_W[t], a1 = p2_W[64 + t], a2 = p2_W[128 + t];
        g_fold.p2s[t] = make_float4(a0 * s1, a1 * s1, a2 * s1, s1);
        g_fold.p2r[t] = make_float4(a0, a1, a2, p2_b[t]);
        g_fold.b1f[t] = w_b1[t] + p2_b[t] * s1;
        g_fold.s1v[t] = s1;
        g_fold.w2[t]  = w2_W[t];
        #pragma unroll
        for (int q = 0; q < 4; q++)
            g_fold.w1p[t * 4 + q] = make_float2(w1_W[t * 8 + 2 * q],
                                                w1_W[t * 8 + 2 * q + 1]);
    }
    if (t < 8) {
        float s2 = w_g2[t] * inv;
        g_fold.s2[t]  = s2;
        g_fold.c2[t]  = w1_b[t] * s2 + w_b2[t];
        g_fold.w2b[t] = w2_b[t];
    }
    if (t < 9) g_fold.pA[t] = p1_W[t] * (p_g[t % 3] * inv);
    if (t < 3) g_fold.pc[t] = p1_b[t] * (p_g[t] * inv) + p_b[t];
}

// ---------------------------------------------------------------------------
// Kernel A: three 64x64 GEMMs with packed f32x2 FMA. grid=(N/64, 3).
// ---------------------------------------------------------------------------
__global__ __launch_bounds__(128) void qkv_kernel(
    const float* __restrict__ x,
    const float* __restrict__ Wq, const float* __restrict__ bq,
    const float* __restrict__ Wk, const float* __restrict__ bk,
    const float* __restrict__ Wv, const float* __restrict__ bv)
{
    __shared__ float Xs[64 * 65];
    __shared__ float Ws[64 * 64];
    __shared__ float Bs[64];

    const int tid = threadIdx.x;
    const int r0  = blockIdx.x * 64;
    const int m   = blockIdx.y;

    const float* W = (m == 0) ? Wq : (m == 1) ? Wk : Wv;
    const float* b = (m == 0) ? bq : (m == 1) ? bk : bv;
    float*       d = (m == 0) ? g_xq : (m == 1) ? g_xk : g_xv;

    for (int idx = tid; idx < 64 * 16; idx += 128) {
        int r = idx >> 4, k4 = (idx & 15) * 4;
        float4 v = *(const float4*)(x + (size_t)(r0 + r) * 64 + k4);
        Xs[r * 65 + k4 + 0] = v.x;
        Xs[r * 65 + k4 + 1] = v.y;
        Xs[r * 65 + k4 + 2] = v.z;
        Xs[r * 65 + k4 + 3] = v.w;
    }
    for (int idx = tid; idx < 64 * 16; idx += 128)
        ((float4*)Ws)[idx] = ((const float4*)W)[idx];
    if (tid < 64) Bs[tid] = b[tid];
    __syncthreads();

    const int tx = tid & 7;   // 8 col groups x 8 cols
    const int ty = tid >> 3;  // rows ty + 16*j

    u64 acc2[4][4];
    #pragma unroll
    for (int j = 0; j < 4; j++)
        #pragma unroll
        for (int i = 0; i < 4; i++) acc2[j][i] = 0ull;

    #pragma unroll 4
    for (int k = 0; k < 64; k++) {
        u64 xap[4];
        #pragma unroll
        for (int j = 0; j < 4; j++) {
            float xa = Xs[(ty + 16 * j) * 65 + k];
            xap[j] = pk2(xa, xa);
        }
        const u64* wp = (const u64*)(Ws + k * 64 + tx * 8);
        u64 wv[4] = {wp[0], wp[1], wp[2], wp[3]};
        #pragma unroll
        for (int j = 0; j < 4; j++)
            #pragma unroll
            for (int i = 0; i < 4; i++)
                ffma2(acc2[j][i], xap[j], wv[i]);
    }

    #pragma unroll
    for (int j = 0; j < 4; j++) {
        size_t off = (size_t)(r0 + ty + 16 * j) * 64 + tx * 8;
        float o[8];
        #pragma unroll
        for (int i = 0; i < 4; i++) {
            float2 v = upk2(acc2[j][i]);
            o[2 * i]     = v.x + Bs[tx * 8 + 2 * i];
            o[2 * i + 1] = v.y + Bs[tx * 8 + 2 * i + 1];
        }
        *(float4*)(d + off)     = make_float4(o[0], o[1], o[2], o[3]);
        *(float4*)(d + off + 4) = make_float4(o[4], o[5], o[6], o[7]);
    }
}

// ---------------------------------------------------------------------------
// Kernel B: attention. 16 points x 16 neighbors per block (256 threads).
// Uniform weights come from __constant__ (const port, off L1). Phase 2 uses
// the softmax-sums-to-one identity to drop the per-(ns,c) position term.
// NOTE: softmax weight group for channel c is c % 8 (CS is the FAST axis of
// the (S, CS) reshape). Phase-2 quads therefore need per-element weights,
// served by a transposed weight layout s_wtT[pt][ns][r] via LDS.128.
// ---------------------------------------------------------------------------
__global__ __launch_bounds__(256, 3) void attn_kernel(
    const float* __restrict__ p,
    const int*   __restrict__ nidx,
    float* __restrict__ out)
{
    __shared__ __align__(16) float s_k[256 * 36]; // k tile chunks -> attn weights
    __shared__ float4 s_base4[256];      // [pt][16 quads]: b1f - xq*s1
    __shared__ float4 s_h4[256];         // (h0,h1,h2,-)
    __shared__ int    s_idx[256];
    __shared__ __align__(16) float s_Hx[128];  // [pt*8+cs]: sum_ns wt*h
    __shared__ __align__(16) float s_Hy[128];
    __shared__ __align__(16) float s_Hz[128];

    const int tid  = threadIdx.x;
    const int blk0 = blockIdx.x * 16;

    // base terms: b1f[c] - xq*s1v[c]  (divergent -> read from g_fold global)
    for (int idx = tid; idx < 16 * 64; idx += 256) {
        int ptl = idx >> 6, c = idx & 63;
        float base = g_fold.b1f[c] - g_xq[(size_t)(blk0 + ptl) * 64 + c] * g_fold.s1v[c];
        ((float*)s_base4)[ptl * 64 + c] = base;
    }

    const int ptl = tid >> 4, ln = tid & 15;
    const int pt  = blk0 + ptl;
    const int j   = nidx[pt * NSN + ln];
    s_idx[tid] = j;

    // position MLP (uniform weights from cmem)
    float h0, h1, h2;
    {
        float dp0 = p[j * 3 + 0] - p[pt * 3 + 0];
        float dp1 = p[j * 3 + 1] - p[pt * 3 + 1];
        float dp2 = p[j * 3 + 2] - p[pt * 3 + 2];
        h0 = fmaxf(fmaf(dp0, c_cw.pA[0], fmaf(dp1, c_cw.pA[3], fmaf(dp2, c_cw.pA[6], c_cw.pc[0]))), 0.f);
        h1 = fmaxf(fmaf(dp0, c_cw.pA[1], fmaf(dp1, c_cw.pA[4], fmaf(dp2, c_cw.pA[7], c_cw.pc[1]))), 0.f);
        h2 = fmaxf(fmaf(dp0, c_cw.pA[2], fmaf(dp1, c_cw.pA[5], fmaf(dp2, c_cw.pA[8], c_cw.pc[2]))), 0.f);
    }
    s_h4[tid] = make_float4(h0, h1, h2, 0.f);
    __syncthreads();

    // ---- phase 1: logits MLP over 2 staged 32-channel chunks ----
    u64 a01 = 0ull, a23 = 0ull, a45 = 0ull, a67 = 0ull;

    #pragma unroll
    for (int ch = 0; ch < 2; ch++) {
        if (ch) __syncthreads();
        {   // cooperative coalesced stage: 8-lane groups load 128B row chunks
            const int q8 = tid & 7;
            const int rb = tid >> 3;
            #pragma unroll
            for (int i = 0; i < 8; i++) {
                int row = rb + 32 * i;
                int jj  = s_idx[row];
                float4 v = *(const float4*)(g_xk + (size_t)jj * 64 + ch * 32 + q8 * 4);
                *(float4*)(s_k + row * 36 + q8 * 4) = v;
            }
        }
        __syncthreads();

        const float4* krow4 = (const float4*)(s_k + tid * 36);
        #pragma unroll
        for (int c4 = 0; c4 < 8; c4++) {
            float4 gk4 = krow4[c4];
            float4 bb  = s_base4[ptl * 16 + ch * 8 + c4];
            float gv[4] = {gk4.x, gk4.y, gk4.z, gk4.w};
            float bl[4] = {bb.x, bb.y, bb.z, bb.w};
            #pragma unroll
            for (int q = 0; q < 4; q++) {
                const int c = ch * 32 + c4 * 4 + q;
                float4 ps = c_cw.p2s[c];
                float a = fmaxf(fmaf(gv[q], ps.w,
                              fmaf(h0, ps.x, fmaf(h1, ps.y, fmaf(h2, ps.z, bl[q])))), 0.f);
                u64 aa = pk2(a, a);
                ffma2(a01, aa, pk2(c_cw.w1p[c * 4 + 0].x, c_cw.w1p[c * 4 + 0].y));
                ffma2(a23, aa, pk2(c_cw.w1p[c * 4 + 1].x, c_cw.w1p[c * 4 + 1].y));
                ffma2(a45, aa, pk2(c_cw.w1p[c * 4 + 2].x, c_cw.w1p[c * 4 + 2].y));
                ffma2(a67, aa, pk2(c_cw.w1p[c * 4 + 3].x, c_cw.w1p[c * 4 + 3].y));
            }
        }
    }
    __syncthreads();  // all k-tile reads done before s_k is reused

    // BN2 + ReLU + w2 -> 8 logits (uniform cmem)
    float lg[8];
    {
        float2 t01 = upk2(a01), t23 = upk2(a23), t45 = upk2(a45), t67 = upk2(a67);
        float ac[8] = {t01.x, t01.y, t23.x, t23.y, t45.x, t45.y, t67.x, t67.y};
        float u[8];
        #pragma unroll
        for (int q = 0; q < 8; q++)
            u[q] = fmaxf(fmaf(ac[q], c_cw.s2[q], c_cw.c2[q]), 0.f);
        #pragma unroll
        for (int rp = 0; rp < 4; rp++) {
            u64 acc = pk2(c_cw.w2b[2 * rp], c_cw.w2b[2 * rp + 1]);
            #pragma unroll
            for (int q = 0; q < 8; q++)
                ffma2(acc, pk2(u[q], u[q]),
                      pk2(c_cw.w2[q * 8 + 2 * rp], c_cw.w2[q * 8 + 2 * rp + 1]));
            float2 v = upk2(acc);
            lg[2 * rp] = v.x; lg[2 * rp + 1] = v.y;
        }
    }

    // softmax over the 16 neighbors (aligned 16-lane group)
    float* s_wt  = s_k;             // [pt*136 + r*17 + ns]   (for H precompute)
    float* s_wtT = s_k + 16 * 136;  // [pt*128 + ns*8 + r]    (for phase 2 LDS.128)
    float wt[8];
    #pragma unroll
    for (int r = 0; r < 8; r++) {
        float m = lg[r];
        m = fmaxf(m, __shfl_xor_sync(0xffffffffu, m, 1));
        m = fmaxf(m, __shfl_xor_sync(0xffffffffu, m, 2));
        m = fmaxf(m, __shfl_xor_sync(0xffffffffu, m, 4));
        m = fmaxf(m, __shfl_xor_sync(0xffffffffu, m, 8));
        float e = __expf(lg[r] - m);
        float s = e;
        s += __shfl_xor_sync(0xffffffffu, s, 1);
        s += __shfl_xor_sync(0xffffffffu, s, 2);
        s += __shfl_xor_sync(0xffffffffu, s, 4);
        s += __shfl_xor_sync(0xffffffffu, s, 8);
        wt[r] = __fdividef(e, s);
        s_wt[ptl * 136 + r * 17 + ln] = wt[r];
    }
    {
        float4* w4 = (float4*)(s_wtT + ptl * 128 + ln * 8);
        w4[0] = make_float4(wt[0], wt[1], wt[2], wt[3]);
        w4[1] = make_float4(wt[4], wt[5], wt[6], wt[7]);
    }
    __syncthreads();

    // ---- H precompute: H[pt][cs] = sum_ns wt[ns,cs] * h[ns]
    if (tid < 128) {
        int pl = tid >> 3, cs = tid & 7;
        float Hx = 0.f, Hy = 0.f, Hz = 0.f;
        #pragma unroll
        for (int ns = 0; ns < 16; ns++) {
            float w = s_wt[pl * 136 + cs * 17 + ns];
            float4 hh = s_h4[pl * 16 + ns];
            Hx = fmaf(w, hh.x, Hx);
            Hy = fmaf(w, hh.y, Hy);
            Hz = fmaf(w, hh.z, Hz);
        }
        s_Hx[tid] = Hx; s_Hy[tid] = Hy; s_Hz[tid] = Hz;
    }
    __syncthreads();

    // ---- phase 2: thread = (point, channel quad c=ln*4..+3), LDG.128 gather.
    // Channel c uses weight group cs = c % 8 = (ln&1)*4 + jc.
    const int half = ln & 1;
    const float* wtp = s_wtT + ptl * 128 + half * 4;
    float4 acc = make_float4(0.f, 0.f, 0.f, 0.f);
    #pragma unroll
    for (int ns = 0; ns < 16; ns++) {
        int jj   = s_idx[ptl * 16 + ns];
        float4 w = *(const float4*)(wtp + ns * 8);
        float4 v = *(const float4*)(g_xv + (size_t)jj * 64 + ln * 4);
        acc.x = fmaf(w.x, v.x, acc.x);
        acc.y = fmaf(w.y, v.y, acc.y);
        acc.z = fmaf(w.z, v.z, acc.z);
        acc.w = fmaf(w.w, v.w, acc.w);
    }
    float4 Hx4 = *(const float4*)(s_Hx + ptl * 8 + half * 4);
    float4 Hy4 = *(const float4*)(s_Hy + ptl * 8 + half * 4);
    float4 Hz4 = *(const float4*)(s_Hz + ptl * 8 + half * 4);
    float4 r;
    #pragma unroll
    for (int jc = 0; jc < 4; jc++) {
        float4 pr = g_fold.p2r[ln * 4 + jc];
        (&r.x)[jc] = (&acc.x)[jc] +
                     fmaf((&Hx4.x)[jc], pr.x,
                     fmaf((&Hy4.x)[jc], pr.y,
                     fmaf((&Hz4.x)[jc], pr.z, pr.w)));
    }
    *(float4*)(out + (size_t)pt * 64 + ln * 4) = r;
}

// ---------------------------------------------------------------------------
extern "C" void kernel_launch(void* const* d_in, const int* in_sizes, int n_in,
                              void* d_out, int out_size)
{
    const float* p    = (const float*)d_in[0];
    const float* x    = (const float*)d_in[1];
    const int*   nidx = (const int*)  d_in[2];
    const float* Wq   = (const float*)d_in[3];
    const float* bq   = (const float*)d_in[4];
    const float* Wk   = (const float*)d_in[5];
    const float* bk   = (const float*)d_in[6];
    const float* Wv   = (const float*)d_in[7];
    const float* bv   = (const float*)d_in[8];
    const float* p1W  = (const float*)d_in[9];
    const float* p1b  = (const float*)d_in[10];
    const float* pg   = (const float*)d_in[11];
    const float* pb   = (const float*)d_in[12];
    const float* p2W  = (const float*)d_in[13];
    const float* p2b  = (const float*)d_in[14];
    const float* wg1  = (const float*)d_in[15];
    const float* wb1  = (const float*)d_in[16];
    const float* w1W  = (const float*)d_in[17];
    const float* w1b  = (const float*)d_in[18];
    const float* wg2  = (const float*)d_in[19];
    const float* wb2  = (const float*)d_in[20];
    const float* w2W  = (const float*)d_in[21];
    const float* w2b  = (const float*)d_in[22];
    float* out = (float*)d_out;

    const int N = in_sizes[1] / CC;   // 65536

    dim3 gq(N / 64, 3);
    qkv_kernel<<<gq, 128>>>(x, Wq, bq, Wk, bk, Wv, bv);

    fold_kernel<<<1, 64>>>(p1W, p1b, pg, pb, p2W, p2b,
                           wg1, wb1, w1W, w1b, wg2, wb2, w2W, w2b);

    void *dst = nullptr, *src = nullptr;
    cudaGetSymbolAddress(&dst, c_cw);
    cudaGetSymbolAddress(&src, g_fold);
    cudaMemcpyAsync(dst, src, sizeof(FW), cudaMemcpyDeviceToDevice, 0);

    attn_kernel<<<N / 16, 256>>>(p, nidx, out);
}

// round 6
// speedup vs baseline: 1.6052x; 1.1293x over previous
#include <cuda_runtime.h>
#include <cstdint>

#define CC 64
#define NSN 16
#define MAXN 65536

typedef unsigned long long u64;

// Scratch — __device__ globals per harness rules.
// g_xq holds the PRE-FOLDED attention base: b1f[c] - (x@Wq+bq)[c]*s1v[c].
__device__ float g_xq[MAXN * CC];
__device__ float g_xk[MAXN * CC];
__device__ float g_xv[MAXN * CC];

// Folded-weight struct: __device__ (divergent access) + __constant__ (uniform).
struct FW {
    float4 p2s[64];     // (p2W0*s1, p2W1*s1, p2W2*s1, s1) per channel
    float4 p2r[64];     // (p2W0, p2W1, p2W2, p2_b) raw
    float2 w1p[256];    // w1[c][2q], w1[c][2q+1]  (c*4+q)
    float  w2[64];      // w2_W[q*8+r]
    float  s2[8], c2[8], w2b[8];
    float  pA[9], pc[3];   // folded position MLP layer 1
    float  b1f[64], s1v[64];
};
__device__ FW g_fold;
__constant__ FW c_cw;

// ---- f32x2 helpers (packed fp32) ----
__device__ __forceinline__ void ffma2(u64& d, u64 a, u64 b) {
    asm("fma.rn.f32x2 %0, %1, %2, %0;" : "+l"(d) : "l"(a), "l"(b));
}
__device__ __forceinline__ u64 pk2(float x, float y) {
    u64 r; asm("mov.b64 %0, {%1, %2};" : "=l"(r) : "f"(x), "f"(y)); return r;
}
__device__ __forceinline__ float2 upk2(u64 v) {
    float2 r; asm("mov.b64 {%0, %1}, %2;" : "=f"(r.x), "=f"(r.y) : "l"(v)); return r;
}

// ---------------------------------------------------------------------------
// Fold kernel: pre-fold BN scales into g_fold (runs BEFORE qkv).
// ---------------------------------------------------------------------------
__global__ void fold_kernel(
    const float* __restrict__ p1_W, const float* __restrict__ p1_b,
    const float* __restrict__ p_g,  const float* __restrict__ p_b,
    const float* __restrict__ p2_W, const float* __restrict__ p2_b,
    const float* __restrict__ w_g1, const float* __restrict__ w_b1,
    const float* __restrict__ w1_W, const float* __restrict__ w1_b,
    const float* __restrict__ w_g2, const float* __restrict__ w_b2,
    const float* __restrict__ w2_W, const float* __restrict__ w2_b)
{
    const int t = threadIdx.x;
    const float inv = rsqrtf(1.0f + 1e-5f);
    if (t < 64) {
        float s1 = w_g1[t] * inv;
        float a0 = p2_W[t], a1 = p2_W[64 + t], a2 = p2_W[128 + t];
        g_fold.p2s[t] = make_float4(a0 * s1, a1 * s1, a2 * s1, s1);
        g_fold.p2r[t] = make_float4(a0, a1, a2, p2_b[t]);
        g_fold.b1f[t] = w_b1[t] + p2_b[t] * s1;
        g_fold.s1v[t] = s1;
        g_fold.w2[t]  = w2_W[t];
        #pragma unroll
        for (int q = 0; q < 4; q++)
            g_fold.w1p[t * 4 + q] = make_float2(w1_W[t * 8 + 2 * q],
                                                w1_W[t * 8 + 2 * q + 1]);
    }
    if (t < 8) {
        float s2 = w_g2[t] * inv;
        g_fold.s2[t]  = s2;
        g_fold.c2[t]  = w1_b[t] * s2 + w_b2[t];
        g_fold.w2b[t] = w2_b[t];
    }
    if (t < 9) g_fold.pA[t] = p1_W[t] * (p_g[t % 3] * inv);
    if (t < 3) g_fold.pc[t] = p1_b[t] * (p_g[t] * inv) + p_b[t];
}

// ---------------------------------------------------------------------------
// Kernel A: three 64x64 GEMMs, 128 rows/block, thread tile 8x8, FFMA2.
// X staged TRANSPOSED (XsT[k][r], 32KB) -> 2 conflict-free LDS.128 per k.
// W read straight from global (16KB, L1-resident) -> 2 LDG.128 per k.
// 4 LSU ops per 32 FFMA2. X staged once, reused for all 3 matrices.
// m==0 epilogue stores the folded attention base into g_xq.
// ---------------------------------------------------------------------------
__global__ __launch_bounds__(128) void qkv_kernel(
    const float* __restrict__ x,
    const float* __restrict__ Wq, const float* __restrict__ bq,
    const float* __restrict__ Wk, const float* __restrict__ bk,
    const float* __restrict__ Wv, const float* __restrict__ bv)
{
    __shared__ float XsT[64][128];   // [k][r], 32 KB

    const int tid = threadIdx.x;
    const int r0  = blockIdx.x * 128;

    // stage + transpose: thread = one row, 16 float4 loads, 64 STS (stride-1)
    {
        const float* xr = x + (size_t)(r0 + tid) * 64;
        #pragma unroll
        for (int k4 = 0; k4 < 16; k4++) {
            float4 v = *(const float4*)(xr + k4 * 4);
            XsT[k4 * 4 + 0][tid] = v.x;
            XsT[k4 * 4 + 1][tid] = v.y;
            XsT[k4 * 4 + 2][tid] = v.z;
            XsT[k4 * 4 + 3][tid] = v.w;
        }
    }
    __syncthreads();

    const int tx = tid & 7;    // col group: cols tx*8 .. +7
    const int ty = tid >> 3;   // row group: rows ty*8 .. +7

    const float* Wm[3] = {Wq, Wk, Wv};
    const float* bm[3] = {bq, bk, bv};

    #pragma unroll
    for (int m = 0; m < 3; m++) {
        const float* W = Wm[m];

        u64 acc[8][4];   // [row][colpair]
        #pragma unroll
        for (int j = 0; j < 8; j++)
            #pragma unroll
            for (int i = 0; i < 4; i++) acc[j][i] = 0ull;

        #pragma unroll 2
        for (int k = 0; k < 64; k++) {
            float4 a0 = *(const float4*)&XsT[k][ty * 8];
            float4 a1 = *(const float4*)&XsT[k][ty * 8 + 4];
            float4 w0 = *(const float4*)(W + k * 64 + tx * 8);
            float4 w1 = *(const float4*)(W + k * 64 + tx * 8 + 4);
            u64 wp[4] = {pk2(w0.x, w0.y), pk2(w0.z, w0.w),
                         pk2(w1.x, w1.y), pk2(w1.z, w1.w)};
            float ar[8] = {a0.x, a0.y, a0.z, a0.w, a1.x, a1.y, a1.z, a1.w};
            #pragma unroll
            for (int j = 0; j < 8; j++) {
                u64 aj = pk2(ar[j], ar[j]);
                #pragma unroll
                for (int i = 0; i < 4; i++)
                    ffma2(acc[j][i], aj, wp[i]);
            }
        }

        // epilogue
        float bias[8];
        #pragma unroll
        for (int i = 0; i < 8; i++) bias[i] = bm[m][tx * 8 + i];

        if (m == 0) {
            float bf[8], sv[8];
            #pragma unroll
            for (int i = 0; i < 8; i++) {
                bf[i] = g_fold.b1f[tx * 8 + i];
                sv[i] = g_fold.s1v[tx * 8 + i];
            }
            #pragma unroll
            for (int j = 0; j < 8; j++) {
                size_t off = (size_t)(r0 + ty * 8 + j) * 64 + tx * 8;
                float o[8];
                #pragma unroll
                for (int i = 0; i < 4; i++) {
                    float2 v = upk2(acc[j][i]);
                    o[2*i]   = bf[2*i]   - (v.x + bias[2*i])   * sv[2*i];
                    o[2*i+1] = bf[2*i+1] - (v.y + bias[2*i+1]) * sv[2*i+1];
                }
                *(float4*)(g_xq + off)     = make_float4(o[0], o[1], o[2], o[3]);
                *(float4*)(g_xq + off + 4) = make_float4(o[4], o[5], o[6], o[7]);
            }
        } else {
            float* d = (m == 1) ? g_xk : g_xv;
            #pragma unroll
            for (int j = 0; j < 8; j++) {
                size_t off = (size_t)(r0 + ty * 8 + j) * 64 + tx * 8;
                float o[8];
                #pragma unroll
                for (int i = 0; i < 4; i++) {
                    float2 v = upk2(acc[j][i]);
                    o[2*i]   = v.x + bias[2*i];
                    o[2*i+1] = v.y + bias[2*i+1];
                }
                *(float4*)(d + off)     = make_float4(o[0], o[1], o[2], o[3]);
                *(float4*)(d + off + 4) = make_float4(o[4], o[5], o[6], o[7]);
            }
        }
    }
}

// ---------------------------------------------------------------------------
// Kernel B: attention. 16 points x 16 neighbors per block (256 threads).
// Same as R5 except base staging is now a plain coalesced copy from g_xq.
// ---------------------------------------------------------------------------
__global__ __launch_bounds__(256, 3) void attn_kernel(
    const float* __restrict__ p,
    const int*   __restrict__ nidx,
    float* __restrict__ out)
{
    __shared__ __align__(16) float s_k[256 * 36]; // k tile chunks -> attn weights
    __shared__ float4 s_base4[256];      // [pt][16 quads]: b1f - xq*s1 (prefolded)
    __shared__ float4 s_h4[256];         // (h0,h1,h2,-)
    __shared__ int    s_idx[256];
    __shared__ __align__(16) float s_Hx[128];  // [pt*8+cs]: sum_ns wt*h
    __shared__ __align__(16) float s_Hy[128];
    __shared__ __align__(16) float s_Hz[128];

    const int tid  = threadIdx.x;
    const int blk0 = blockIdx.x * 16;

    // base terms: straight coalesced copy (prefolded in qkv epilogue)
    s_base4[tid] = *(const float4*)(g_xq + (size_t)blk0 * 64 + tid * 4);

    const int ptl = tid >> 4, ln = tid & 15;
    const int pt  = blk0 + ptl;
    const int j   = nidx[pt * NSN + ln];
    s_idx[tid] = j;

    // position MLP (uniform weights from cmem)
    float h0, h1, h2;
    {
        float dp0 = p[j * 3 + 0] - p[pt * 3 + 0];
        float dp1 = p[j * 3 + 1] - p[pt * 3 + 1];
        float dp2 = p[j * 3 + 2] - p[pt * 3 + 2];
        h0 = fmaxf(fmaf(dp0, c_cw.pA[0], fmaf(dp1, c_cw.pA[3], fmaf(dp2, c_cw.pA[6], c_cw.pc[0]))), 0.f);
        h1 = fmaxf(fmaf(dp0, c_cw.pA[1], fmaf(dp1, c_cw.pA[4], fmaf(dp2, c_cw.pA[7], c_cw.pc[1]))), 0.f);
        h2 = fmaxf(fmaf(dp0, c_cw.pA[2], fmaf(dp1, c_cw.pA[5], fmaf(dp2, c_cw.pA[8], c_cw.pc[2]))), 0.f);
    }
    s_h4[tid] = make_float4(h0, h1, h2, 0.f);
    __syncthreads();

    // ---- phase 1: logits MLP over 2 staged 32-channel chunks ----
    u64 a01 = 0ull, a23 = 0ull, a45 = 0ull, a67 = 0ull;

    #pragma unroll
    for (int ch = 0; ch < 2; ch++) {
        if (ch) __syncthreads();
        {   // cooperative coalesced stage: 8-lane groups load 128B row chunks
            const int q8 = tid & 7;
            const int rb = tid >> 3;
            #pragma unroll
            for (int i = 0; i < 8; i++) {
                int row = rb + 32 * i;
                int jj  = s_idx[row];
                float4 v = *(const float4*)(g_xk + (size_t)jj * 64 + ch * 32 + q8 * 4);
                *(float4*)(s_k + row * 36 + q8 * 4) = v;
            }
        }
        __syncthreads();

        const float4* krow4 = (const float4*)(s_k + tid * 36);
        #pragma unroll
        for (int c4 = 0; c4 < 8; c4++) {
            float4 gk4 = krow4[c4];
            float4 bb  = s_base4[ptl * 16 + ch * 8 + c4];
            float gv[4] = {gk4.x, gk4.y, gk4.z, gk4.w};
            float bl[4] = {bb.x, bb.y, bb.z, bb.w};
            #pragma unroll
            for (int q = 0; q < 4; q++) {
                const int c = ch * 32 + c4 * 4 + q;
                float4 ps = c_cw.p2s[c];
                float a = fmaxf(fmaf(gv[q], ps.w,
                              fmaf(h0, ps.x, fmaf(h1, ps.y, fmaf(h2, ps.z, bl[q])))), 0.f);
                u64 aa = pk2(a, a);
                ffma2(a01, aa, pk2(c_cw.w1p[c * 4 + 0].x, c_cw.w1p[c * 4 + 0].y));
                ffma2(a23, aa, pk2(c_cw.w1p[c * 4 + 1].x, c_cw.w1p[c * 4 + 1].y));
                ffma2(a45, aa, pk2(c_cw.w1p[c * 4 + 2].x, c_cw.w1p[c * 4 + 2].y));
                ffma2(a67, aa, pk2(c_cw.w1p[c * 4 + 3].x, c_cw.w1p[c * 4 + 3].y));
            }
        }
    }
    __syncthreads();  // all k-tile reads done before s_k is reused

    // BN2 + ReLU + w2 -> 8 logits (uniform cmem)
    float lg[8];
    {
        float2 t01 = upk2(a01), t23 = upk2(a23), t45 = upk2(a45), t67 = upk2(a67);
        float ac[8] = {t01.x, t01.y, t23.x, t23.y, t45.x, t45.y, t67.x, t67.y};
        float u[8];
        #pragma unroll
        for (int q = 0; q < 8; q++)
            u[q] = fmaxf(fmaf(ac[q], c_cw.s2[q], c_cw.c2[q]), 0.f);
        #pragma unroll
        for (int rp = 0; rp < 4; rp++) {
            u64 acc = pk2(c_cw.w2b[2 * rp], c_cw.w2b[2 * rp + 1]);
            #pragma unroll
            for (int q = 0; q < 8; q++)
                ffma2(acc, pk2(u[q], u[q]),
                      pk2(c_cw.w2[q * 8 + 2 * rp], c_cw.w2[q * 8 + 2 * rp + 1]));
            float2 v = upk2(acc);
            lg[2 * rp] = v.x; lg[2 * rp + 1] = v.y;
        }
    }

    // softmax over the 16 neighbors (aligned 16-lane group)
    float* s_wt  = s_k;             // [pt*136 + r*17 + ns]   (for H precompute)
    float* s_wtT = s_k + 16 * 136;  // [pt*128 + ns*8 + r]    (for phase 2 LDS.128)
    float wt[8];
    #pragma unroll
    for (int r = 0; r < 8; r++) {
        float m = lg[r];
        m = fmaxf(m, __shfl_xor_sync(0xffffffffu, m, 1));
        m = fmaxf(m, __shfl_xor_sync(0xffffffffu, m, 2));
        m = fmaxf(m, __shfl_xor_sync(0xffffffffu, m, 4));
        m = fmaxf(m, __shfl_xor_sync(0xffffffffu, m, 8));
        float e = __expf(lg[r] - m);
        float s = e;
        s += __shfl_xor_sync(0xffffffffu, s, 1);
        s += __shfl_xor_sync(0xffffffffu, s, 2);
        s += __shfl_xor_sync(0xffffffffu, s, 4);
        s += __shfl_xor_sync(0xffffffffu, s, 8);
        wt[r] = __fdividef(e, s);
        s_wt[ptl * 136 + r * 17 + ln] = wt[r];
    }
    {
        float4* w4 = (float4*)(s_wtT + ptl * 128 + ln * 8);
        w4[0] = make_float4(wt[0], wt[1], wt[2], wt[3]);
        w4[1] = make_float4(wt[4], wt[5], wt[6], wt[7]);
    }
    __syncthreads();

    // ---- H precompute: H[pt][cs] = sum_ns wt[ns,cs] * h[ns]
    if (tid < 128) {
        int pl = tid >> 3, cs = tid & 7;
        float Hx = 0.f, Hy = 0.f, Hz = 0.f;
        #pragma unroll
        for (int ns = 0; ns < 16; ns++) {
            float w = s_wt[pl * 136 + cs * 17 + ns];
            float4 hh = s_h4[pl * 16 + ns];
            Hx = fmaf(w, hh.x, Hx);
            Hy = fmaf(w, hh.y, Hy);
            Hz = fmaf(w, hh.z, Hz);
        }
        s_Hx[tid] = Hx; s_Hy[tid] = Hy; s_Hz[tid] = Hz;
    }
    __syncthreads();

    // ---- phase 2: thread = (point, channel quad c=ln*4..+3), LDG.128 gather.
    // Channel c uses weight group cs = c % 8 = (ln&1)*4 + jc.
    const int half = ln & 1;
    const float* wtp = s_wtT + ptl * 128 + half * 4;
    float4 acc = make_float4(0.f, 0.f, 0.f, 0.f);
    #pragma unroll
    for (int ns = 0; ns < 16; ns++) {
        int jj   = s_idx[ptl * 16 + ns];
        float4 w = *(const float4*)(wtp + ns * 8);
        float4 v = *(const float4*)(g_xv + (size_t)jj * 64 + ln * 4);
        acc.x = fmaf(w.x, v.x, acc.x);
        acc.y = fmaf(w.y, v.y, acc.y);
        acc.z = fmaf(w.z, v.z, acc.z);
        acc.w = fmaf(w.w, v.w, acc.w);
    }
    float4 Hx4 = *(const float4*)(s_Hx + ptl * 8 + half * 4);
    float4 Hy4 = *(const float4*)(s_Hy + ptl * 8 + half * 4);
    float4 Hz4 = *(const float4*)(s_Hz + ptl * 8 + half * 4);
    float4 r;
    #pragma unroll
    for (int jc = 0; jc < 4; jc++) {
        float4 pr = g_fold.p2r[ln * 4 + jc];
        (&r.x)[jc] = (&acc.x)[jc] +
                     fmaf((&Hx4.x)[jc], pr.x,
                     fmaf((&Hy4.x)[jc], pr.y,
                     fmaf((&Hz4.x)[jc], pr.z, pr.w)));
    }
    *(float4*)(out + (size_t)pt * 64 + ln * 4) = r;
}

// ---------------------------------------------------------------------------
extern "C" void kernel_launch(void* const* d_in, const int* in_sizes, int n_in,
                              void* d_out, int out_size)
{
    const float* p    = (const float*)d_in[0];
    const float* x    = (const float*)d_in[1];
    const int*   nidx = (const int*)  d_in[2];
    const float* Wq   = (const float*)d_in[3];
    const float* bq   = (const float*)d_in[4];
    const float* Wk   = (const float*)d_in[5];
    const float* bk   = (const float*)d_in[6];
    const float* Wv   = (const float*)d_in[7];
    const float* bv   = (const float*)d_in[8];
    const float* p1W  = (const float*)d_in[9];
    const float* p1b  = (const float*)d_in[10];
    const float* pg   = (const float*)d_in[11];
    const float* pb   = (const float*)d_in[12];
    const float* p2W  = (const float*)d_in[13];
    const float* p2b  = (const float*)d_in[14];
    const float* wg1  = (const float*)d_in[15];
    const float* wb1  = (const float*)d_in[16];
    const float* w1W  = (const float*)d_in[17];
    const float* w1b  = (const float*)d_in[18];
    const float* wg2  = (const float*)d_in[19];
    const float* wb2  = (const float*)d_in[20];
    const float* w2W  = (const float*)d_in[21];
    const float* w2b  = (const float*)d_in[22];
    float* out = (float*)d_out;

    const int N = in_sizes[1] / CC;   // 65536

    fold_kernel<<<1, 64>>>(p1W, p1b, pg, pb, p2W, p2b,
                           wg1, wb1, w1W, w1b, wg2, wb2, w2W, w2b);

    void *dst = nullptr, *src = nullptr;
    cudaGetSymbolAddress(&dst, c_cw);
    cudaGetSymbolAddress(&src, g_fold);
    cudaMemcpyAsync(dst, src, sizeof(FW), cudaMemcpyDeviceToDevice, 0);

    qkv_kernel<<<N / 128, 128>>>(x, Wq, bq, Wk, bk, Wv, bv);

    attn_kernel<<<N / 16, 256>>>(p, nidx, out);
}

// round 7
// speedup vs baseline: 1.8756x; 1.1684x over previous
#include <cuda_runtime.h>
#include <cstdint>

#define CC 64
#define NSN 16
#define MAXN 65536

typedef unsigned long long u64;

// Scratch — __device__ globals per harness rules.
// g_xq holds the PRE-FOLDED attention base: b1f[c] - (x@Wq+bq)[c]*s1v[c].
__device__ float g_xq[MAXN * CC];
__device__ float g_xk[MAXN * CC];
__device__ float g_xv[MAXN * CC];

// Folded-weight struct: __device__ (divergent access) + __constant__ (uniform).
struct FW {
    float4 p2s[64];     // (p2W0*s1, p2W1*s1, p2W2*s1, s1) per channel
    float4 p2r[64];     // (p2W0, p2W1, p2W2, p2_b) raw
    float2 w1p[256];    // w1[c][2q], w1[c][2q+1]  (c*4+q)
    float  w2[64];      // w2_W[q*8+r]
    float  s2[8], c2[8], w2b[8];
    float  pA[9], pc[3];   // folded position MLP layer 1
    float  b1f[64], s1v[64];
};
__device__ FW g_fold;
__constant__ FW c_cw;

// ---- f32x2 helpers (packed fp32) ----
__device__ __forceinline__ void ffma2(u64& d, u64 a, u64 b) {
    asm("fma.rn.f32x2 %0, %1, %2, %0;" : "+l"(d) : "l"(a), "l"(b));
}
__device__ __forceinline__ u64 pk2(float x, float y) {
    u64 r; asm("mov.b64 %0, {%1, %2};" : "=l"(r) : "f"(x), "f"(y)); return r;
}
__device__ __forceinline__ float2 upk2(u64 v) {
    float2 r; asm("mov.b64 {%0, %1}, %2;" : "=f"(r.x), "=f"(r.y) : "l"(v)); return r;
}
__device__ __forceinline__ uint32_t smem_u32(const void* ptr) {
    uint32_t a;
    asm("{ .reg .u64 t; cvta.to.shared.u64 t, %1; cvt.u32.u64 %0, t; }"
        : "=r"(a) : "l"(ptr));
    return a;
}
__device__ __forceinline__ void cp_async16(uint32_t dst, const void* src) {
    asm volatile("cp.async.cg.shared.global [%0], [%1], 16;\n"
                 :: "r"(dst), "l"(src));
}

// ---------------------------------------------------------------------------
// Fold kernel: parallel pre-fold of BN scales into g_fold (256 threads).
// ---------------------------------------------------------------------------
__global__ __launch_bounds__(256) void fold_kernel(
    const float* __restrict__ p1_W, const float* __restrict__ p1_b,
    const float* __restrict__ p_g,  const float* __restrict__ p_b,
    const float* __restrict__ p2_W, const float* __restrict__ p2_b,
    const float* __restrict__ w_g1, const float* __restrict__ w_b1,
    const float* __restrict__ w1_W, const float* __restrict__ w1_b,
    const float* __restrict__ w_g2, const float* __restrict__ w_b2,
    const float* __restrict__ w2_W, const float* __restrict__ w2_b)
{
    const int t = threadIdx.x;
    const float inv = rsqrtf(1.0f + 1e-5f);

    // w1p: 256 entries, one per thread
    {
        int c = t >> 2, q = t & 3;
        g_fold.w1p[t] = make_float2(w1_W[c * 8 + 2 * q], w1_W[c * 8 + 2 * q + 1]);
    }
    if (t < 64) {
        float s1 = w_g1[t] * inv;
        float a0 = p2_W[t], a1 = p2_W[64 + t], a2 = p2_W[128 + t];
        g_fold.p2s[t] = make_float4(a0 * s1, a1 * s1, a2 * s1, s1);
        g_fold.p2r[t] = make_float4(a0, a1, a2, p2_b[t]);
        g_fold.b1f[t] = w_b1[t] + p2_b[t] * s1;
        g_fold.s1v[t] = s1;
    } else if (t < 128) {
        g_fold.w2[t - 64] = w2_W[t - 64];
    } else if (t < 136) {
        int q = t - 128;
        float s2 = w_g2[q] * inv;
        g_fold.s2[q]  = s2;
        g_fold.c2[q]  = w1_b[q] * s2 + w_b2[q];
        g_fold.w2b[q] = w2_b[q];
    } else if (t < 145) {
        int q = t - 136;
        g_fold.pA[q] = p1_W[q] * (p_g[q % 3] * inv);
    } else if (t < 148) {
        int q = t - 145;
        g_fold.pc[q] = p1_b[q] * (p_g[q] * inv) + p_b[q];
    }
}

// ---------------------------------------------------------------------------
// Kernel A: three 64x64 GEMMs, 128 rows/block, thread tile 8x8, FFMA2.
// (~90% of the fp32 CUDA-core floor; unchanged from R6.)
// ---------------------------------------------------------------------------
__global__ __launch_bounds__(128) void qkv_kernel(
    const float* __restrict__ x,
    const float* __restrict__ Wq, const float* __restrict__ bq,
    const float* __restrict__ Wk, const float* __restrict__ bk,
    const float* __restrict__ Wv, const float* __restrict__ bv)
{
    __shared__ float XsT[64][128];   // [k][r], 32 KB

    const int tid = threadIdx.x;
    const int r0  = blockIdx.x * 128;

    {
        const float* xr = x + (size_t)(r0 + tid) * 64;
        #pragma unroll
        for (int k4 = 0; k4 < 16; k4++) {
            float4 v = *(const float4*)(xr + k4 * 4);
            XsT[k4 * 4 + 0][tid] = v.x;
            XsT[k4 * 4 + 1][tid] = v.y;
            XsT[k4 * 4 + 2][tid] = v.z;
            XsT[k4 * 4 + 3][tid] = v.w;
        }
    }
    __syncthreads();

    const int tx = tid & 7;
    const int ty = tid >> 3;

    const float* Wm[3] = {Wq, Wk, Wv};
    const float* bm[3] = {bq, bk, bv};

    #pragma unroll
    for (int m = 0; m < 3; m++) {
        const float* W = Wm[m];

        u64 acc[8][4];
        #pragma unroll
        for (int j = 0; j < 8; j++)
            #pragma unroll
            for (int i = 0; i < 4; i++) acc[j][i] = 0ull;

        #pragma unroll 2
        for (int k = 0; k < 64; k++) {
            float4 a0 = *(const float4*)&XsT[k][ty * 8];
            float4 a1 = *(const float4*)&XsT[k][ty * 8 + 4];
            float4 w0 = *(const float4*)(W + k * 64 + tx * 8);
            float4 w1 = *(const float4*)(W + k * 64 + tx * 8 + 4);
            u64 wp[4] = {pk2(w0.x, w0.y), pk2(w0.z, w0.w),
                         pk2(w1.x, w1.y), pk2(w1.z, w1.w)};
            float ar[8] = {a0.x, a0.y, a0.z, a0.w, a1.x, a1.y, a1.z, a1.w};
            #pragma unroll
            for (int j = 0; j < 8; j++) {
                u64 aj = pk2(ar[j], ar[j]);
                #pragma unroll
                for (int i = 0; i < 4; i++)
                    ffma2(acc[j][i], aj, wp[i]);
            }
        }

        float bias[8];
        #pragma unroll
        for (int i = 0; i < 8; i++) bias[i] = bm[m][tx * 8 + i];

        if (m == 0) {
            float bf[8], sv[8];
            #pragma unroll
            for (int i = 0; i < 8; i++) {
                bf[i] = g_fold.b1f[tx * 8 + i];
                sv[i] = g_fold.s1v[tx * 8 + i];
            }
            #pragma unroll
            for (int j = 0; j < 8; j++) {
                size_t off = (size_t)(r0 + ty * 8 + j) * 64 + tx * 8;
                float o[8];
                #pragma unroll
                for (int i = 0; i < 4; i++) {
                    float2 v = upk2(acc[j][i]);
                    o[2*i]   = bf[2*i]   - (v.x + bias[2*i])   * sv[2*i];
                    o[2*i+1] = bf[2*i+1] - (v.y + bias[2*i+1]) * sv[2*i+1];
                }
                *(float4*)(g_xq + off)     = make_float4(o[0], o[1], o[2], o[3]);
                *(float4*)(g_xq + off + 4) = make_float4(o[4], o[5], o[6], o[7]);
            }
        } else {
            float* d = (m == 1) ? g_xk : g_xv;
            #pragma unroll
            for (int j = 0; j < 8; j++) {
                size_t off = (size_t)(r0 + ty * 8 + j) * 64 + tx * 8;
                float o[8];
                #pragma unroll
                for (int i = 0; i < 4; i++) {
                    float2 v = upk2(acc[j][i]);
                    o[2*i]   = v.x + bias[2*i];
                    o[2*i+1] = v.y + bias[2*i+1];
                }
                *(float4*)(d + off)     = make_float4(o[0], o[1], o[2], o[3]);
                *(float4*)(d + off + 4) = make_float4(o[4], o[5], o[6], o[7]);
            }
        }
    }
}

// ---------------------------------------------------------------------------
// Kernel B: attention. 16 points x 16 neighbors per block (256 threads).
// R7: cp.async staging (no reg round-trip) + 4 blocks/SM target.
// ---------------------------------------------------------------------------
__global__ __launch_bounds__(256, 4) void attn_kernel(
    const float* __restrict__ p,
    const int*   __restrict__ nidx,
    float* __restrict__ out)
{
    __shared__ __align__(16) float s_k[256 * 36]; // k tile chunks -> attn weights
    __shared__ float4 s_base4[256];      // [pt][16 quads]: b1f - xq*s1 (prefolded)
    __shared__ float4 s_h4[256];         // (h0,h1,h2,-)
    __shared__ int    s_idx[256];
    __shared__ __align__(16) float s_Hx[128];  // [pt*8+cs]: sum_ns wt*h
    __shared__ __align__(16) float s_Hy[128];
    __shared__ __align__(16) float s_Hz[128];

    const int tid  = threadIdx.x;
    const int blk0 = blockIdx.x * 16;

    // base terms: straight coalesced copy (prefolded in qkv epilogue)
    s_base4[tid] = *(const float4*)(g_xq + (size_t)blk0 * 64 + tid * 4);

    const int ptl = tid >> 4, ln = tid & 15;
    const int pt  = blk0 + ptl;
    const int j   = nidx[pt * NSN + ln];
    s_idx[tid] = j;

    // position MLP (uniform weights from cmem)
    float h0, h1, h2;
    {
        float dp0 = p[j * 3 + 0] - p[pt * 3 + 0];
        float dp1 = p[j * 3 + 1] - p[pt * 3 + 1];
        float dp2 = p[j * 3 + 2] - p[pt * 3 + 2];
        h0 = fmaxf(fmaf(dp0, c_cw.pA[0], fmaf(dp1, c_cw.pA[3], fmaf(dp2, c_cw.pA[6], c_cw.pc[0]))), 0.f);
        h1 = fmaxf(fmaf(dp0, c_cw.pA[1], fmaf(dp1, c_cw.pA[4], fmaf(dp2, c_cw.pA[7], c_cw.pc[1]))), 0.f);
        h2 = fmaxf(fmaf(dp0, c_cw.pA[2], fmaf(dp1, c_cw.pA[5], fmaf(dp2, c_cw.pA[8], c_cw.pc[2]))), 0.f);
    }
    s_h4[tid] = make_float4(h0, h1, h2, 0.f);
    __syncthreads();

    // ---- phase 1: logits MLP over 2 cp.async-staged 32-channel chunks ----
    u64 a01 = 0ull, a23 = 0ull, a45 = 0ull, a67 = 0ull;

    const uint32_t s_k_base = smem_u32(s_k);

    #pragma unroll
    for (int ch = 0; ch < 2; ch++) {
        if (ch) __syncthreads();  // chunk-0 reads done before overwrite
        {   // cooperative coalesced stage via cp.async (16B per op)
            const int q8 = tid & 7;
            const int rb = tid >> 3;
            #pragma unroll
            for (int i = 0; i < 8; i++) {
                int row = rb + 32 * i;
                int jj  = s_idx[row];
                cp_async16(s_k_base + (row * 36 + q8 * 4) * 4,
                           g_xk + (size_t)jj * 64 + ch * 32 + q8 * 4);
            }
            asm volatile("cp.async.commit_group;\n" ::: "memory");
            asm volatile("cp.async.wait_group 0;\n" ::: "memory");
        }
        __syncthreads();

        const float4* krow4 = (const float4*)(s_k + tid * 36);
        #pragma unroll
        for (int c4 = 0; c4 < 8; c4++) {
            float4 gk4 = krow4[c4];
            float4 bb  = s_base4[ptl * 16 + ch * 8 + c4];
            float gv[4] = {gk4.x, gk4.y, gk4.z, gk4.w};
            float bl[4] = {bb.x, bb.y, bb.z, bb.w};
            #pragma unroll
            for (int q = 0; q < 4; q++) {
                const int c = ch * 32 + c4 * 4 + q;
                float4 ps = c_cw.p2s[c];
                float a = fmaxf(fmaf(gv[q], ps.w,
                              fmaf(h0, ps.x, fmaf(h1, ps.y, fmaf(h2, ps.z, bl[q])))), 0.f);
                u64 aa = pk2(a, a);
                ffma2(a01, aa, pk2(c_cw.w1p[c * 4 + 0].x, c_cw.w1p[c * 4 + 0].y));
                ffma2(a23, aa, pk2(c_cw.w1p[c * 4 + 1].x, c_cw.w1p[c * 4 + 1].y));
                ffma2(a45, aa, pk2(c_cw.w1p[c * 4 + 2].x, c_cw.w1p[c * 4 + 2].y));
                ffma2(a67, aa, pk2(c_cw.w1p[c * 4 + 3].x, c_cw.w1p[c * 4 + 3].y));
            }
        }
    }
    __syncthreads();  // all k-tile reads done before s_k is reused

    // BN2 + ReLU + w2 -> 8 logits (uniform cmem)
    float lg[8];
    {
        float2 t01 = upk2(a01), t23 = upk2(a23), t45 = upk2(a45), t67 = upk2(a67);
        float ac[8] = {t01.x, t01.y, t23.x, t23.y, t45.x, t45.y, t67.x, t67.y};
        float u[8];
        #pragma unroll
        for (int q = 0; q < 8; q++)
            u[q] = fmaxf(fmaf(ac[q], c_cw.s2[q], c_cw.c2[q]), 0.f);
        #pragma unroll
        for (int rp = 0; rp < 4; rp++) {
            u64 acc = pk2(c_cw.w2b[2 * rp], c_cw.w2b[2 * rp + 1]);
            #pragma unroll
            for (int q = 0; q < 8; q++)
                ffma2(acc, pk2(u[q], u[q]),
                      pk2(c_cw.w2[q * 8 + 2 * rp], c_cw.w2[q * 8 + 2 * rp + 1]));
            float2 v = upk2(acc);
            lg[2 * rp] = v.x; lg[2 * rp + 1] = v.y;
        }
    }

    // softmax over the 16 neighbors (aligned 16-lane group)
    float* s_wt  = s_k;             // [pt*136 + r*17 + ns]   (for H precompute)
    float* s_wtT = s_k + 16 * 136;  // [pt*128 + ns*8 + r]    (for phase 2 LDS.128)
    float wt[8];
    #pragma unroll
    for (int r = 0; r < 8; r++) {
        float m = lg[r];
        m = fmaxf(m, __shfl_xor_sync(0xffffffffu, m, 1));
        m = fmaxf(m, __shfl_xor_sync(0xffffffffu, m, 2));
        m = fmaxf(m, __shfl_xor_sync(0xffffffffu, m, 4));
        m = fmaxf(m, __shfl_xor_sync(0xffffffffu, m, 8));
        float e = __expf(lg[r] - m);
        float s = e;
        s += __shfl_xor_sync(0xffffffffu, s, 1);
        s += __shfl_xor_sync(0xffffffffu, s, 2);
        s += __shfl_xor_sync(0xffffffffu, s, 4);
        s += __shfl_xor_sync(0xffffffffu, s, 8);
        wt[r] = __fdividef(e, s);
        s_wt[ptl * 136 + r * 17 + ln] = wt[r];
    }
    {
        float4* w4 = (float4*)(s_wtT + ptl * 128 + ln * 8);
        w4[0] = make_float4(wt[0], wt[1], wt[2], wt[3]);
        w4[1] = make_float4(wt[4], wt[5], wt[6], wt[7]);
    }
    __syncthreads();

    // ---- H precompute: H[pt][cs] = sum_ns wt[ns,cs] * h[ns]
    if (tid < 128) {
        int pl = tid >> 3, cs = tid & 7;
        float Hx = 0.f, Hy = 0.f, Hz = 0.f;
        #pragma unroll
        for (int ns = 0; ns < 16; ns++) {
            float w = s_wt[pl * 136 + cs * 17 + ns];
            float4 hh = s_h4[pl * 16 + ns];
            Hx = fmaf(w, hh.x, Hx);
            Hy = fmaf(w, hh.y, Hy);
            Hz = fmaf(w, hh.z, Hz);
        }
        s_Hx[tid] = Hx; s_Hy[tid] = Hy; s_Hz[tid] = Hz;
    }
    __syncthreads();

    // ---- phase 2: thread = (point, channel quad c=ln*4..+3), LDG.128 gather.
    // Channel c uses weight group cs = c % 8 = (ln&1)*4 + jc.
    const int half = ln & 1;
    const float* wtp = s_wtT + ptl * 128 + half * 4;
    float4 acc = make_float4(0.f, 0.f, 0.f, 0.f);
    #pragma unroll
    for (int ns = 0; ns < 16; ns++) {
        int jj   = s_idx[ptl * 16 + ns];
        float4 w = *(const float4*)(wtp + ns * 8);
        float4 v = *(const float4*)(g_xv + (size_t)jj * 64 + ln * 4);
        acc.x = fmaf(w.x, v.x, acc.x);
        acc.y = fmaf(w.y, v.y, acc.y);
        acc.z = fmaf(w.z, v.z, acc.z);
        acc.w = fmaf(w.w, v.w, acc.w);
    }
    float4 Hx4 = *(const float4*)(s_Hx + ptl * 8 + half * 4);
    float4 Hy4 = *(const float4*)(s_Hy + ptl * 8 + half * 4);
    float4 Hz4 = *(const float4*)(s_Hz + ptl * 8 + half * 4);
    float4 r;
    #pragma unroll
    for (int jc = 0; jc < 4; jc++) {
        float4 pr = g_fold.p2r[ln * 4 + jc];
        (&r.x)[jc] = (&acc.x)[jc] +
                     fmaf((&Hx4.x)[jc], pr.x,
                     fmaf((&Hy4.x)[jc], pr.y,
                     fmaf((&Hz4.x)[jc], pr.z, pr.w)));
    }
    *(float4*)(out + (size_t)pt * 64 + ln * 4) = r;
}

// ---------------------------------------------------------------------------
extern "C" void kernel_launch(void* const* d_in, const int* in_sizes, int n_in,
                              void* d_out, int out_size)
{
    const float* p    = (const float*)d_in[0];
    const float* x    = (const float*)d_in[1];
    const int*   nidx = (const int*)  d_in[2];
    const float* Wq   = (const float*)d_in[3];
    const float* bq   = (const float*)d_in[4];
    const float* Wk   = (const float*)d_in[5];
    const float* bk   = (const float*)d_in[6];
    const float* Wv   = (const float*)d_in[7];
    const float* bv   = (const float*)d_in[8];
    const float* p1W  = (const float*)d_in[9];
    const float* p1b  = (const float*)d_in[10];
    const float* pg   = (const float*)d_in[11];
    const float* pb   = (const float*)d_in[12];
    const float* p2W  = (const float*)d_in[13];
    const float* p2b  = (const float*)d_in[14];
    const float* wg1  = (const float*)d_in[15];
    const float* wb1  = (const float*)d_in[16];
    const float* w1W  = (const float*)d_in[17];
    const float* w1b  = (const float*)d_in[18];
    const float* wg2  = (const float*)d_in[19];
    const float* wb2  = (const float*)d_in[20];
    const float* w2W  = (const float*)d_in[21];
    const float* w2b  = (const float*)d_in[22];
    float* out = (float*)d_out;

    const int N = in_sizes[1] / CC;   // 65536

    fold_kernel<<<1, 256>>>(p1W, p1b, pg, pb, p2W, p2b,
                            wg1, wb1, w1W, w1b, wg2, wb2, w2W, w2b);

    void *dst = nullptr, *src = nullptr;
    cudaGetSymbolAddress(&dst, c_cw);
    cudaGetSymbolAddress(&src, g_fold);
    cudaMemcpyAsync(dst, src, sizeof(FW), cudaMemcpyDeviceToDevice, 0);

    qkv_kernel<<<N / 128, 128>>>(x, Wq, bq, Wk, bk, Wv, bv);

    attn_kernel<<<N / 16, 256>>>(p, nidx, out);
}